// round 5
// baseline (speedup 1.0000x reference)
#include <cuda_runtime.h>

// PhiCell: Phi is identity => outputs = inputs * k; new_state = outputs[T-1].
// Streaming scale. Read-side limited (writes absorbed by L2), so:
//  - 8 front-batched LDG.128 per thread (deep MLP)
//  - streaming stores (__stcs, evict-first) to keep L2 capacity for the input

#define VPT 8  // float4 vectors per thread

__global__ void __launch_bounds__(256) phicell_v8(
    const float4* __restrict__ in4,
    const float*  __restrict__ kptr,
    float4*       __restrict__ out4,
    int n4,
    const float* __restrict__ in_scalar,
    float* __restrict__ out_scalar,
    int n, int out_size)
{
    const int tid  = threadIdx.x;
    const int base = blockIdx.x * (blockDim.x * VPT) + tid;

    float4 v[VPT];
    int    idx[VPT];
    bool   ok[VPT];

    // Front-batched independent loads -> MLP_p1 = 8
#pragma unroll
    for (int j = 0; j < VPT; ++j) {
        idx[j] = base + j * (int)blockDim.x;
        ok[j]  = idx[j] < n4;
        if (ok[j]) v[j] = __ldg(&in4[idx[j]]);
    }

    const float k = __ldg(kptr);

#pragma unroll
    for (int j = 0; j < VPT; ++j) {
        if (ok[j]) {
            v[j].x *= k; v[j].y *= k; v[j].z *= k; v[j].w *= k;
            __stcs(&out4[idx[j]], v[j]);   // streaming store: evict-first in L2
            if (idx[j] == n4 - 1 && (n4 << 2) == n) {
                for (int s = n; s < out_size; ++s) out_scalar[s] = v[j].w;
            }
        }
    }

    // Scalar remainder (n % 4 != 0) + state slots
    if ((n & 3) && blockIdx.x == 0 && tid == 0) {
        float last = 0.f;
        for (int i = n4 << 2; i < n; ++i) {
            last = in_scalar[i] * k;
            out_scalar[i] = last;
        }
        for (int s = n; s < out_size; ++s) out_scalar[s] = last;
    }
}

extern "C" void kernel_launch(void* const* d_in, const int* in_sizes, int n_in,
                              void* d_out, int out_size)
{
    const float* in  = (const float*)d_in[0];   // inputs [1, T]
    // d_in[1] = state [1,1] (unused: Phi identity -> output state-independent)
    const float* kpt = (const float*)d_in[2];   // kernel [1,1]
    float* out = (float*)d_out;

    const int n   = in_sizes[0];
    const int n4  = n >> 2;
    const int thr = 256;
    const int per_block = thr * VPT;
    const int blk = (n4 + per_block - 1) / per_block;

    phicell_v8<<<blk > 0 ? blk : 1, thr>>>(
        (const float4*)in, kpt, (float4*)out, n4,
        in, out, n, out_size);
}